// round 8
// baseline (speedup 1.0000x reference)
#include <cuda_runtime.h>
#include <cuda_fp16.h>
#include <math.h>
#include <stdint.h>

// ----------------------------- problem constants -----------------------------
#define BB    4
#define TT    8192
#define CC    1024
#define MROWS (BB * TT)       // 32768
#define KP    2048            // split-K: A'=[hi|lo] (fp16), W'=[hi|hi]
#define NCH   64
#define CHUNK 128             // NCH * CHUNK == TT

// GEMM tiling: CTA 128x256, warp 64x64, BK=64, swizzled 128B rows
#define BM     128
#define BN     256
#define BK     64
#define ROWB   128                      // bytes per row (64 fp16), XOR-swizzled
#define A_TILE (BM * ROWB)              // 16384 B
#define B_TILE (BN * ROWB)              // 32768 B
#define STG_SZ (A_TILE + B_TILE)        // 49152 B
#define NSTG   3
#define NCHUNKS (KP / BK)               // 32
#define SMEM_DYN (NSTG * STG_SZ)        // 147456 B

// -------- scratch (device globals; no runtime allocation allowed) --------
__device__ __half g_a   [(size_t)MROWS * KP];   // ln output, split layout
__device__ __half g_att2[(size_t)MROWS * KP];   // attention, split layout
__device__ __half g_w   [(size_t)4 * CC * KP];  // Wk,Wv,Wr,Wo split layout
__device__ float g_k  [(size_t)MROWS * CC];
__device__ float g_v  [(size_t)MROWS * CC];
__device__ float g_r  [(size_t)MROWS * CC];
__device__ float g_csum[(size_t)BB * NCH * CC];

// ----------------------------- PTX helpers -----------------------------
__device__ __forceinline__ uint32_t smem_u32(const void* p) {
    uint32_t a;
    asm("{ .reg .u64 t; cvta.to.shared.u64 t, %1; cvt.u32.u64 %0, t; }" : "=r"(a) : "l"(p));
    return a;
}
__device__ __forceinline__ void cp16(uint32_t dst, const void* src) {
    asm volatile("cp.async.cg.shared.global [%0], [%1], 16;" :: "r"(dst), "l"(src));
}
__device__ __forceinline__ void cp_commit() {
    asm volatile("cp.async.commit_group;" ::: "memory");
}
__device__ __forceinline__ void cp_wait1() {
    asm volatile("cp.async.wait_group 1;" ::: "memory");
}
__device__ __forceinline__ void ldm_x4(uint32_t* f, uint32_t addr) {
    asm volatile("ldmatrix.sync.aligned.m8n8.x4.shared.b16 {%0,%1,%2,%3}, [%4];"
                 : "=r"(f[0]), "=r"(f[1]), "=r"(f[2]), "=r"(f[3]) : "r"(addr));
}
__device__ __forceinline__ void mma16816(float* c, const uint32_t* a, const uint32_t* b) {
    asm volatile("mma.sync.aligned.m16n8k16.row.col.f32.f16.f16.f32 "
                 "{%0,%1,%2,%3}, {%4,%5,%6,%7}, {%8,%9}, {%0,%1,%2,%3};"
                 : "+f"(c[0]), "+f"(c[1]), "+f"(c[2]), "+f"(c[3])
                 : "r"(a[0]), "r"(a[1]), "r"(a[2]), "r"(a[3]), "r"(b[0]), "r"(b[1]));
}

// dummy kernel: aligns ncu capture (launch #3 == gemm_kvr)
__global__ void nop_kernel() {}

// ======================= LayerNorm -> split fp16 layout =======================
__global__ void ln_kernel(const float* __restrict__ x,
                          const float* __restrict__ ln_w,
                          const float* __restrict__ ln_b) {
    int gwarp = (blockIdx.x * blockDim.x + threadIdx.x) >> 5;
    int lane  = threadIdx.x & 31;
    if (gwarp >= MROWS) return;

    const float4* xr = (const float4*)(x + (size_t)gwarp * CC);
    const float4* wr = (const float4*)ln_w;
    const float4* br = (const float4*)ln_b;

    float4 vals[8];
    float s = 0.f, s2 = 0.f;
#pragma unroll
    for (int i = 0; i < 8; i++) {
        float4 v = xr[lane + i * 32];
        vals[i] = v;
        s  += v.x + v.y + v.z + v.w;
        s2 += v.x * v.x + v.y * v.y + v.z * v.z + v.w * v.w;
    }
#pragma unroll
    for (int off = 16; off; off >>= 1) {
        s  += __shfl_xor_sync(0xffffffffu, s,  off);
        s2 += __shfl_xor_sync(0xffffffffu, s2, off);
    }
    const float inv = 1.0f / (float)CC;
    float mu  = s * inv;
    float var = s2 * inv - mu * mu;
    float rstd = rsqrtf(var + 1e-5f);

    __half* arow = g_a + (size_t)gwarp * KP;
#pragma unroll
    for (int i = 0; i < 8; i++) {
        float4 v = vals[i];
        float4 w = wr[lane + i * 32];
        float4 b = br[lane + i * 32];
        float o0 = (v.x - mu) * rstd * w.x + b.x;
        float o1 = (v.y - mu) * rstd * w.y + b.y;
        float o2 = (v.z - mu) * rstd * w.z + b.z;
        float o3 = (v.w - mu) * rstd * w.w + b.w;
        __half h0 = __float2half_rn(o0);
        __half h1 = __float2half_rn(o1);
        __half h2 = __float2half_rn(o2);
        __half h3 = __float2half_rn(o3);
        __half l0 = __float2half_rn(o0 - __half2float(h0));
        __half l1 = __float2half_rn(o1 - __half2float(h1));
        __half l2 = __float2half_rn(o2 - __half2float(h2));
        __half l3 = __float2half_rn(o3 - __half2float(h3));
        int col = (lane + i * 32) * 4;
        __half2 H0 = __halves2half2(h0, h1);
        __half2 H1 = __halves2half2(h2, h3);
        __half2 L0 = __halves2half2(l0, l1);
        __half2 L1 = __halves2half2(l2, l3);
        *(__half2*)(arow + col)            = H0;
        *(__half2*)(arow + col + 2)        = H1;
        *(__half2*)(arow + 1024 + col)     = L0;
        *(__half2*)(arow + 1024 + col + 2) = L1;
    }
}

// =================== weight conversion to split fp16 layout ===================
__global__ void wconv(const float* __restrict__ Wk, const float* __restrict__ Wv,
                      const float* __restrict__ Wr, const float* __restrict__ Wo) {
    size_t idx  = (size_t)blockIdx.x * blockDim.x + threadIdx.x;
    size_t base = idx * 4;
    int w = (int)(base >> 20);
    size_t rem = base & 0xFFFFFu;
    const float* W = (w == 0) ? Wk : (w == 1) ? Wv : (w == 2) ? Wr : Wo;
    float4 v = *(const float4*)(W + rem);
    __half h0 = __float2half_rn(v.x);
    __half h1 = __float2half_rn(v.y);
    __half h2 = __float2half_rn(v.z);
    __half h3 = __float2half_rn(v.w);
    size_t row = rem >> 10;
    size_t k   = rem & 1023u;
    __half* dst = g_w + ((size_t)w * CC + row) * KP + k;
    __half2 H0 = __halves2half2(h0, h1);
    __half2 H1 = __halves2half2(h2, h3);
    *(__half2*)(dst)            = H0;
    *(__half2*)(dst + 2)        = H1;
    *(__half2*)(dst + 1024)     = H0;
    *(__half2*)(dst + 1024 + 2) = H1;
}

// ============== fp16 mma.sync NT GEMM: C[M,N] = A'[M,KP] * W'[N,KP]^T ==============
// CTA 128x256, warp tile 64x64, BK=64, XOR-swizzled 128B smem rows.
__global__ void __launch_bounds__(256)
gemm_mma(float* __restrict__ out, int isKVR) {
    extern __shared__ __align__(1024) char smem[];
    const uint32_t sbase = smem_u32(smem);

    const int tid  = threadIdx.x;
    const int lane = tid & 31;
    const int wid  = tid >> 5;
    const int wm   = wid & 1;     // 2 warp-rows (64 each)
    const int wn   = wid >> 1;    // 4 warp-cols (64 each)

    int col, w;
    if (isKVR) { w = blockIdx.x % 3; col = blockIdx.x / 3; }
    else       { w = 3;              col = blockIdx.x;     }
    const int brow = blockIdx.y * BM;
    const int bcol = col * BN;

    const __half* Abase = (isKVR ? g_a : g_att2) + (size_t)brow * KP;
    const __half* Wbase = g_w + ((size_t)w * CC + bcol) * KP;

    // ldmatrix per-lane swizzled address components.
    uint32_t abase[4], axor[4];
#pragma unroll
    for (int mt = 0; mt < 4; mt++) {
        int rowA = wm * 64 + mt * 16 + (lane & 15);
        int s = rowA & 7;
        abase[mt] = (uint32_t)(rowA * ROWB + (((lane >> 4) ^ (s & 1)) << 4));
        axor[mt]  = (uint32_t)((s & 6) << 4);
    }
    uint32_t bbase[4], bxor[4];
#pragma unroll
    for (int ntp = 0; ntp < 4; ntp++) {
        int rowB = wn * 64 + ntp * 16 + ((lane >> 4) << 3) + (lane & 7);
        int s = rowB & 7;
        bbase[ntp] = (uint32_t)(rowB * ROWB + ((((lane >> 3) & 1) ^ (s & 1)) << 4));
        bxor[ntp]  = (uint32_t)((s & 6) << 4);
    }

    float acc[4][8][4];
#pragma unroll
    for (int mt = 0; mt < 4; mt++)
#pragma unroll
        for (int nt = 0; nt < 8; nt++)
#pragma unroll
            for (int j = 0; j < 4; j++) acc[mt][nt][j] = 0.f;

    // ---- async load of one stage (BK=64: 8 chunks of 16B per row) ----
    auto load_stage = [&](int stg, int chunk) {
        uint32_t sA = sbase + stg * STG_SZ;
        uint32_t sB = sA + A_TILE;
        const __half* Ap = Abase + chunk * BK;
        const __half* Wp = Wbase + chunk * BK;
#pragma unroll
        for (int t = tid; t < BM * 8; t += 256) {
            int r = t >> 3, c = t & 7;
            uint32_t off = (uint32_t)(r * ROWB + ((c ^ (r & 7)) << 4));
            cp16(sA + off, Ap + (size_t)r * KP + c * 8);
        }
#pragma unroll
        for (int t = tid; t < BN * 8; t += 256) {
            int r = t >> 3, c = t & 7;
            uint32_t off = (uint32_t)(r * ROWB + ((c ^ (r & 7)) << 4));
            cp16(sB + off, Wp + (size_t)r * KP + c * 8);
        }
    };

    load_stage(0, 0); cp_commit();
    load_stage(1, 1); cp_commit();

    for (int i = 0; i < NCHUNKS; i++) {
        cp_wait1();
        __syncthreads();
        if (i + 2 < NCHUNKS) load_stage((i + 2) % NSTG, i + 2);
        cp_commit();

        uint32_t sA = sbase + (i % NSTG) * STG_SZ;
        uint32_t sB = sA + A_TILE;
#pragma unroll
        for (int kh = 0; kh < 4; kh++) {
            uint32_t kb = (uint32_t)(kh * 32);
            uint32_t af[4][4], bf[8][2];
#pragma unroll
            for (int mt = 0; mt < 4; mt++)
                ldm_x4(af[mt], sA + abase[mt] + (kb ^ axor[mt]));
#pragma unroll
            for (int ntp = 0; ntp < 4; ntp++) {
                uint32_t t4[4];
                ldm_x4(t4, sB + bbase[ntp] + (kb ^ bxor[ntp]));
                bf[ntp * 2 + 0][0] = t4[0]; bf[ntp * 2 + 0][1] = t4[1];
                bf[ntp * 2 + 1][0] = t4[2]; bf[ntp * 2 + 1][1] = t4[3];
            }
#pragma unroll
            for (int mt = 0; mt < 4; mt++)
#pragma unroll
                for (int nt = 0; nt < 8; nt++)
                    mma16816(acc[mt][nt], af[mt], bf[nt]);
        }
    }

    // ---- epilogue: fp32 direct to global ----
    float* Cm;
    if (isKVR) Cm = (w == 0) ? g_k : (w == 1) ? g_v : g_r;
    else       Cm = out;
    const int r0 = brow + wm * 64 + (lane >> 2);
    const int c0 = bcol + wn * 64 + (lane & 3) * 2;
#pragma unroll
    for (int mt = 0; mt < 4; mt++) {
#pragma unroll
        for (int nt = 0; nt < 8; nt++) {
            float* p0 = Cm + (size_t)(r0 + mt * 16) * CC + c0 + nt * 8;
            float* p1 = p0 + 8 * CC;
            *(float2*)p0 = make_float2(acc[mt][nt][0], acc[mt][nt][1]);
            *(float2*)p1 = make_float2(acc[mt][nt][2], acc[mt][nt][3]);
        }
    }
}

// ======================= WKV scan (chunked 2-pass) =======================
__global__ void scan_partial(const float* __restrict__ time_decay) {
    int c  = blockIdx.x * 256 + threadIdx.x;
    int ch = blockIdx.y;
    int b  = blockIdx.z;
    float td = -expf(time_decay[c]);
    size_t base = ((size_t)(b * TT + ch * CHUNK)) * CC + c;
    float s = 0.f;
#pragma unroll 4
    for (int i = 0; i < CHUNK; i++) {
        float t = (float)(ch * CHUNK + i);
        float w = expf(td * t);
        size_t id = base + (size_t)i * CC;
        s += g_k[id] * g_v[id] * w;
    }
    g_csum[((size_t)b * NCH + ch) * CC + c] = s;
}

// pass 2: inline exclusive chunk-prefix + replay; writes split-fp16 att
__global__ void scan_final(const float* __restrict__ time_decay,
                           const float* __restrict__ time_first) {
    int c  = blockIdx.x * 256 + threadIdx.x;
    int ch = blockIdx.y;
    int b  = blockIdx.z;
    float td = -expf(time_decay[c]);
    float tf = expf(time_first[c]);

    float state = 0.f;
    for (int j = 0; j < ch; j++)
        state += g_csum[((size_t)b * NCH + j) * CC + c];

    size_t rowbase = (size_t)(b * TT + ch * CHUNK);
#pragma unroll 4
    for (int i = 0; i < CHUNK; i++) {
        size_t id = (rowbase + i) * CC + c;
        float kk = g_k[id];
        float vv = g_v[id];
        float rr = g_r[id];
        float wgt = expf(td * (float)(ch * CHUNK + i));
        float sig = 1.0f / (1.0f + expf(-rr));
        float av  = sig * (state + kk * tf);
        state += kk * vv * wgt;
        __half h = __float2half_rn(av);
        __half l = __float2half_rn(av - __half2float(h));
        __half* arow = g_att2 + (rowbase + i) * KP + c;
        arow[0]    = h;
        arow[1024] = l;
    }
}

// ================================ launch ================================
extern "C" void kernel_launch(void* const* d_in, const int* in_sizes, int n_in,
                              void* d_out, int out_size) {
    const float* x          = (const float*)d_in[0];
    const float* time_decay = (const float*)d_in[1];
    const float* time_first = (const float*)d_in[2];
    const float* Wk         = (const float*)d_in[3];
    const float* Wv         = (const float*)d_in[4];
    const float* Wr         = (const float*)d_in[5];
    const float* Wo         = (const float*)d_in[6];
    const float* ln_w       = (const float*)d_in[7];
    const float* ln_b       = (const float*)d_in[8];
    float* out = (float*)d_out;

    cudaFuncSetAttribute(gemm_mma, cudaFuncAttributeMaxDynamicSharedMemorySize, SMEM_DYN);

    // 1) LayerNorm -> g_a (split fp16); weights -> g_w (split fp16)
    ln_kernel<<<MROWS / 8, 256>>>(x, ln_w, ln_b);                 // launch #0
    wconv<<<4096, 256>>>(Wk, Wv, Wr, Wo);                         // launch #1
    nop_kernel<<<1, 32>>>();                                      // launch #2 (ncu align)

    // 2) k, v, r projections (launch #3 -> captured by ncu -s 5 -c 1)
    gemm_mma<<<dim3(12, MROWS / BM), 256, SMEM_DYN>>>(nullptr, 1);

    // 3) WKV scan (2-pass; final inlines the chunk-prefix)
    scan_partial<<<dim3(CC / 256, NCH, BB), 256>>>(time_decay);
    scan_final<<<dim3(CC / 256, NCH, BB), 256>>>(time_decay, time_first);

    // 4) output projection -> d_out
    gemm_mma<<<dim3(4, MROWS / BM), 256, SMEM_DYN>>>(out, 0);
}

// round 9
// speedup vs baseline: 1.7865x; 1.7865x over previous
#include <cuda_runtime.h>
#include <cuda_fp16.h>
#include <math.h>
#include <stdint.h>

// ----------------------------- problem constants -----------------------------
#define BB    4
#define TT    8192
#define CC    1024
#define MROWS (BB * TT)       // 32768
#define KP    1024            // plain fp16 GEMM, no split
#define NCH   64
#define CHUNK 128             // NCH * CHUNK == TT

// GEMM tiling (R7-proven): CTA 128x128, warp 64x32, BK=64, swizzled 128B rows
#define BM     128
#define BN     128
#define BK     64
#define ROWB   128                      // bytes per row (64 fp16), XOR-swizzled
#define TILE_SZ (BM * ROWB)             // 16384 B
#define STG_SZ  (2 * TILE_SZ)           // A tile + B tile = 32768 B
#define NSTG    3
#define NCHUNKS (KP / BK)               // 16
#define SMEM_DYN (NSTG * STG_SZ)        // 98304 B

// -------- scratch (device globals; no runtime allocation allowed) --------
__device__ __half g_a   [(size_t)MROWS * KP];   // ln output (fp16)
__device__ __half g_att2[(size_t)MROWS * KP];   // attention (fp16)
__device__ __half g_w   [(size_t)4 * CC * KP];  // Wk,Wv,Wr,Wo (fp16)
__device__ float g_k  [(size_t)MROWS * CC];
__device__ float g_v  [(size_t)MROWS * CC];
__device__ float g_r  [(size_t)MROWS * CC];
__device__ float g_csum[(size_t)BB * NCH * CC];

// ----------------------------- PTX helpers -----------------------------
__device__ __forceinline__ uint32_t smem_u32(const void* p) {
    uint32_t a;
    asm("{ .reg .u64 t; cvta.to.shared.u64 t, %1; cvt.u32.u64 %0, t; }" : "=r"(a) : "l"(p));
    return a;
}
__device__ __forceinline__ void cp16(uint32_t dst, const void* src) {
    asm volatile("cp.async.cg.shared.global [%0], [%1], 16;" :: "r"(dst), "l"(src));
}
__device__ __forceinline__ void cp_commit() {
    asm volatile("cp.async.commit_group;" ::: "memory");
}
__device__ __forceinline__ void cp_wait1() {
    asm volatile("cp.async.wait_group 1;" ::: "memory");
}
__device__ __forceinline__ void ldm_x4(uint32_t* f, uint32_t addr) {
    asm volatile("ldmatrix.sync.aligned.m8n8.x4.shared.b16 {%0,%1,%2,%3}, [%4];"
                 : "=r"(f[0]), "=r"(f[1]), "=r"(f[2]), "=r"(f[3]) : "r"(addr));
}
__device__ __forceinline__ void mma16816(float* c, const uint32_t* a, const uint32_t* b) {
    asm volatile("mma.sync.aligned.m16n8k16.row.col.f32.f16.f16.f32 "
                 "{%0,%1,%2,%3}, {%4,%5,%6,%7}, {%8,%9}, {%0,%1,%2,%3};"
                 : "+f"(c[0]), "+f"(c[1]), "+f"(c[2]), "+f"(c[3])
                 : "r"(a[0]), "r"(a[1]), "r"(a[2]), "r"(a[3]), "r"(b[0]), "r"(b[1]));
}

// dummy kernel: aligns ncu capture (launch #3 == gemm_kvr)
__global__ void nop_kernel() {}

// ======================= LayerNorm -> fp16 =======================
__global__ void ln_kernel(const float* __restrict__ x,
                          const float* __restrict__ ln_w,
                          const float* __restrict__ ln_b) {
    int gwarp = (blockIdx.x * blockDim.x + threadIdx.x) >> 5;
    int lane  = threadIdx.x & 31;
    if (gwarp >= MROWS) return;

    const float4* xr = (const float4*)(x + (size_t)gwarp * CC);
    const float4* wr = (const float4*)ln_w;
    const float4* br = (const float4*)ln_b;

    float4 vals[8];
    float s = 0.f, s2 = 0.f;
#pragma unroll
    for (int i = 0; i < 8; i++) {
        float4 v = xr[lane + i * 32];
        vals[i] = v;
        s  += v.x + v.y + v.z + v.w;
        s2 += v.x * v.x + v.y * v.y + v.z * v.z + v.w * v.w;
    }
#pragma unroll
    for (int off = 16; off; off >>= 1) {
        s  += __shfl_xor_sync(0xffffffffu, s,  off);
        s2 += __shfl_xor_sync(0xffffffffu, s2, off);
    }
    const float inv = 1.0f / (float)CC;
    float mu  = s * inv;
    float var = s2 * inv - mu * mu;
    float rstd = rsqrtf(var + 1e-5f);

    __half* arow = g_a + (size_t)gwarp * KP;
#pragma unroll
    for (int i = 0; i < 8; i++) {
        float4 v = vals[i];
        float4 w = wr[lane + i * 32];
        float4 b = br[lane + i * 32];
        float o0 = (v.x - mu) * rstd * w.x + b.x;
        float o1 = (v.y - mu) * rstd * w.y + b.y;
        float o2 = (v.z - mu) * rstd * w.z + b.z;
        float o3 = (v.w - mu) * rstd * w.w + b.w;
        int col = (lane + i * 32) * 4;
        *(__half2*)(arow + col)     = __halves2half2(__float2half_rn(o0), __float2half_rn(o1));
        *(__half2*)(arow + col + 2) = __halves2half2(__float2half_rn(o2), __float2half_rn(o3));
    }
}

// =================== weight conversion to fp16 ===================
__global__ void wconv(const float* __restrict__ Wk, const float* __restrict__ Wv,
                      const float* __restrict__ Wr, const float* __restrict__ Wo) {
    size_t idx  = (size_t)blockIdx.x * blockDim.x + threadIdx.x;
    size_t base = idx * 4;
    int w = (int)(base >> 20);
    size_t rem = base & 0xFFFFFu;
    const float* W = (w == 0) ? Wk : (w == 1) ? Wv : (w == 2) ? Wr : Wo;
    float4 v = *(const float4*)(W + rem);
    __half* dst = g_w + ((size_t)w << 20) + rem;
    *(__half2*)(dst)     = __halves2half2(__float2half_rn(v.x), __float2half_rn(v.y));
    *(__half2*)(dst + 2) = __halves2half2(__float2half_rn(v.z), __float2half_rn(v.w));
}

// ============== fp16 mma.sync NT GEMM: C[M,N] = A[M,K] * W[N,K]^T ==============
// BK=64, XOR-swizzled 128B smem rows, ldmatrix x4 for A and B. (R7 tiling)
__global__ void __launch_bounds__(256, 2)
gemm_mma(float* __restrict__ out, int isKVR) {
    extern __shared__ __align__(1024) char smem[];
    const uint32_t sbase = smem_u32(smem);

    const int tid  = threadIdx.x;
    const int lane = tid & 31;
    const int wid  = tid >> 5;
    const int wm   = wid & 1;     // 2 warp-rows (64 each)
    const int wn   = wid >> 1;    // 4 warp-cols (32 each)

    int col, w;
    if (isKVR) { w = blockIdx.x % 3; col = blockIdx.x / 3; }
    else       { w = 3;              col = blockIdx.x;     }
    const int brow = blockIdx.y * BM;
    const int bcol = col * BN;

    const __half* Abase = (isKVR ? g_a : g_att2) + (size_t)brow * KP;
    const __half* Wbase = g_w + ((size_t)w * CC + bcol) * KP;

    // ldmatrix per-lane swizzled address components.
    uint32_t abase[4], axor[4];
#pragma unroll
    for (int mt = 0; mt < 4; mt++) {
        int rowA = wm * 64 + mt * 16 + (lane & 15);
        int s = rowA & 7;
        abase[mt] = (uint32_t)(rowA * ROWB + (((lane >> 4) ^ (s & 1)) << 4));
        axor[mt]  = (uint32_t)((s & 6) << 4);
    }
    uint32_t bbase[2], bxor[2];
#pragma unroll
    for (int ntp = 0; ntp < 2; ntp++) {
        int rowB = wn * 32 + ntp * 16 + ((lane >> 4) << 3) + (lane & 7);
        int s = rowB & 7;
        bbase[ntp] = (uint32_t)(rowB * ROWB + ((((lane >> 3) & 1) ^ (s & 1)) << 4));
        bxor[ntp]  = (uint32_t)((s & 6) << 4);
    }

    float acc[4][4][4];
#pragma unroll
    for (int mt = 0; mt < 4; mt++)
#pragma unroll
        for (int nt = 0; nt < 4; nt++)
#pragma unroll
            for (int j = 0; j < 4; j++) acc[mt][nt][j] = 0.f;

    // ---- async load of one stage (BK=64: 8 chunks of 16B per row) ----
    auto load_stage = [&](int stg, int chunk) {
        uint32_t sA = sbase + stg * STG_SZ;
        uint32_t sB = sA + TILE_SZ;
        const __half* Ap = Abase + chunk * BK;
        const __half* Wp = Wbase + chunk * BK;
#pragma unroll
        for (int t = tid; t < 1024; t += 256) {
            int r = t >> 3, c = t & 7;
            uint32_t off = (uint32_t)(r * ROWB + ((c ^ (r & 7)) << 4));
            cp16(sA + off, Ap + (size_t)r * KP + c * 8);
            cp16(sB + off, Wp + (size_t)r * KP + c * 8);
        }
    };

    load_stage(0, 0); cp_commit();
    load_stage(1, 1); cp_commit();

    for (int i = 0; i < NCHUNKS; i++) {
        cp_wait1();
        __syncthreads();
        if (i + 2 < NCHUNKS) load_stage((i + 2) % NSTG, i + 2);
        cp_commit();

        uint32_t sA = sbase + (i % NSTG) * STG_SZ;
        uint32_t sB = sA + TILE_SZ;
#pragma unroll
        for (int kh = 0; kh < 4; kh++) {
            uint32_t kb = (uint32_t)(kh * 32);
            uint32_t af[4][4], bf[4][2];
#pragma unroll
            for (int mt = 0; mt < 4; mt++)
                ldm_x4(af[mt], sA + abase[mt] + (kb ^ axor[mt]));
#pragma unroll
            for (int ntp = 0; ntp < 2; ntp++) {
                uint32_t t4[4];
                ldm_x4(t4, sB + bbase[ntp] + (kb ^ bxor[ntp]));
                bf[ntp * 2 + 0][0] = t4[0]; bf[ntp * 2 + 0][1] = t4[1];
                bf[ntp * 2 + 1][0] = t4[2]; bf[ntp * 2 + 1][1] = t4[3];
            }
#pragma unroll
            for (int mt = 0; mt < 4; mt++)
#pragma unroll
                for (int nt = 0; nt < 4; nt++)
                    mma16816(acc[mt][nt], af[mt], bf[nt]);
        }
    }

    // ---- epilogue: fp32 direct to global ----
    float* Cm;
    if (isKVR) Cm = (w == 0) ? g_k : (w == 1) ? g_v : g_r;
    else       Cm = out;
    const int r0 = brow + wm * 64 + (lane >> 2);
    const int c0 = bcol + wn * 32 + (lane & 3) * 2;
#pragma unroll
    for (int mt = 0; mt < 4; mt++) {
#pragma unroll
        for (int nt = 0; nt < 4; nt++) {
            float* p0 = Cm + (size_t)(r0 + mt * 16) * CC + c0 + nt * 8;
            float* p1 = p0 + 8 * CC;
            *(float2*)p0 = make_float2(acc[mt][nt][0], acc[mt][nt][1]);
            *(float2*)p1 = make_float2(acc[mt][nt][2], acc[mt][nt][3]);
        }
    }
}

// ======================= WKV scan (chunked 2-pass) =======================
__global__ void scan_partial(const float* __restrict__ time_decay) {
    int c  = blockIdx.x * 256 + threadIdx.x;
    int ch = blockIdx.y;
    int b  = blockIdx.z;
    float td = -expf(time_decay[c]);
    size_t base = ((size_t)(b * TT + ch * CHUNK)) * CC + c;
    float s = 0.f;
#pragma unroll 4
    for (int i = 0; i < CHUNK; i++) {
        float t = (float)(ch * CHUNK + i);
        float w = expf(td * t);
        size_t id = base + (size_t)i * CC;
        s += g_k[id] * g_v[id] * w;
    }
    g_csum[((size_t)b * NCH + ch) * CC + c] = s;
}

// pass 2: inline exclusive chunk-prefix + replay; writes fp16 att
__global__ void scan_final(const float* __restrict__ time_decay,
                           const float* __restrict__ time_first) {
    int c  = blockIdx.x * 256 + threadIdx.x;
    int ch = blockIdx.y;
    int b  = blockIdx.z;
    float td = -expf(time_decay[c]);
    float tf = expf(time_first[c]);

    float state = 0.f;
    for (int j = 0; j < ch; j++)
        state += g_csum[((size_t)b * NCH + j) * CC + c];

    size_t rowbase = (size_t)(b * TT + ch * CHUNK);
#pragma unroll 4
    for (int i = 0; i < CHUNK; i++) {
        size_t id = (rowbase + i) * CC + c;
        float kk = g_k[id];
        float vv = g_v[id];
        float rr = g_r[id];
        float wgt = expf(td * (float)(ch * CHUNK + i));
        float sig = 1.0f / (1.0f + expf(-rr));
        float av  = sig * (state + kk * tf);
        state += kk * vv * wgt;
        g_att2[(rowbase + i) * KP + c] = __float2half_rn(av);
    }
}

// ================================ launch ================================
extern "C" void kernel_launch(void* const* d_in, const int* in_sizes, int n_in,
                              void* d_out, int out_size) {
    const float* x          = (const float*)d_in[0];
    const float* time_decay = (const float*)d_in[1];
    const float* time_first = (const float*)d_in[2];
    const float* Wk         = (const float*)d_in[3];
    const float* Wv         = (const float*)d_in[4];
    const float* Wr         = (const float*)d_in[5];
    const float* Wo         = (const float*)d_in[6];
    const float* ln_w       = (const float*)d_in[7];
    const float* ln_b       = (const float*)d_in[8];
    float* out = (float*)d_out;

    cudaFuncSetAttribute(gemm_mma, cudaFuncAttributeMaxDynamicSharedMemorySize, SMEM_DYN);

    // 1) LayerNorm -> g_a (fp16); weights -> g_w (fp16)
    ln_kernel<<<MROWS / 8, 256>>>(x, ln_w, ln_b);                 // launch #0
    wconv<<<4096, 256>>>(Wk, Wv, Wr, Wo);                         // launch #1
    nop_kernel<<<1, 32>>>();                                      // launch #2 (ncu align)

    // 2) k, v, r projections (launch #3 -> captured by ncu -s 5 -c 1)
    gemm_mma<<<dim3(24, MROWS / BM), 256, SMEM_DYN>>>(nullptr, 1);

    // 3) WKV scan (2-pass; final inlines the chunk-prefix)
    scan_partial<<<dim3(CC / 256, NCH, BB), 256>>>(time_decay);
    scan_final<<<dim3(CC / 256, NCH, BB), 256>>>(time_decay, time_first);

    // 4) output projection -> d_out
    gemm_mma<<<dim3(8, MROWS / BM), 256, SMEM_DYN>>>(out, 0);
}

// round 10
// speedup vs baseline: 1.8392x; 1.0295x over previous
#include <cuda_runtime.h>
#include <cuda_fp16.h>
#include <math.h>
#include <stdint.h>

// ----------------------------- problem constants -----------------------------
#define BB    4
#define TT    8192
#define CC    1024
#define MROWS (BB * TT)       // 32768
#define KP    1024            // plain fp16 GEMM, no split
#define NCH   64
#define CHUNK 128             // NCH * CHUNK == TT

// GEMM tiling: CTA 128x128 (4 warps), warp tile 64x64, BK=64, swizzled 128B rows
#define BM     128
#define BN     128
#define BK     64
#define ROWB   128                      // bytes per row (64 fp16), XOR-swizzled
#define TILE_SZ (BM * ROWB)             // 16384 B
#define STG_SZ  (2 * TILE_SZ)           // A tile + B tile = 32768 B
#define NSTG    3
#define NCHUNKS (KP / BK)               // 16
#define SMEM_DYN (NSTG * STG_SZ)        // 98304 B -> 2 CTAs/SM

// -------- scratch (device globals; no runtime allocation allowed) --------
__device__ __half g_a   [(size_t)MROWS * KP];   // ln output (fp16)
__device__ __half g_att2[(size_t)MROWS * KP];   // attention (fp16)
__device__ __half g_w   [(size_t)4 * CC * KP];  // Wk,Wv,Wr,Wo (fp16)
__device__ __half g_k  [(size_t)MROWS * CC];    // fp16 projections
__device__ __half g_v  [(size_t)MROWS * CC];
__device__ __half g_r  [(size_t)MROWS * CC];
__device__ float g_csum[(size_t)BB * NCH * CC];

// ----------------------------- PTX helpers -----------------------------
__device__ __forceinline__ uint32_t smem_u32(const void* p) {
    uint32_t a;
    asm("{ .reg .u64 t; cvta.to.shared.u64 t, %1; cvt.u32.u64 %0, t; }" : "=r"(a) : "l"(p));
    return a;
}
__device__ __forceinline__ void cp16(uint32_t dst, const void* src) {
    asm volatile("cp.async.cg.shared.global [%0], [%1], 16;" :: "r"(dst), "l"(src));
}
__device__ __forceinline__ void cp_commit() {
    asm volatile("cp.async.commit_group;" ::: "memory");
}
__device__ __forceinline__ void cp_wait1() {
    asm volatile("cp.async.wait_group 1;" ::: "memory");
}
__device__ __forceinline__ void ldm_x4(uint32_t* f, uint32_t addr) {
    asm volatile("ldmatrix.sync.aligned.m8n8.x4.shared.b16 {%0,%1,%2,%3}, [%4];"
                 : "=r"(f[0]), "=r"(f[1]), "=r"(f[2]), "=r"(f[3]) : "r"(addr));
}
__device__ __forceinline__ void mma16816(float* c, const uint32_t* a, const uint32_t* b) {
    asm volatile("mma.sync.aligned.m16n8k16.row.col.f32.f16.f16.f32 "
                 "{%0,%1,%2,%3}, {%4,%5,%6,%7}, {%8,%9}, {%0,%1,%2,%3};"
                 : "+f"(c[0]), "+f"(c[1]), "+f"(c[2]), "+f"(c[3])
                 : "r"(a[0]), "r"(a[1]), "r"(a[2]), "r"(a[3]), "r"(b[0]), "r"(b[1]));
}

// dummy kernel: aligns ncu capture (launch #3 == gemm_kvr)
__global__ void nop_kernel() {}

// ======================= LayerNorm -> fp16 =======================
__global__ void ln_kernel(const float* __restrict__ x,
                          const float* __restrict__ ln_w,
                          const float* __restrict__ ln_b) {
    int gwarp = (blockIdx.x * blockDim.x + threadIdx.x) >> 5;
    int lane  = threadIdx.x & 31;
    if (gwarp >= MROWS) return;

    const float4* xr = (const float4*)(x + (size_t)gwarp * CC);
    const float4* wr = (const float4*)ln_w;
    const float4* br = (const float4*)ln_b;

    float4 vals[8];
    float s = 0.f, s2 = 0.f;
#pragma unroll
    for (int i = 0; i < 8; i++) {
        float4 v = xr[lane + i * 32];
        vals[i] = v;
        s  += v.x + v.y + v.z + v.w;
        s2 += v.x * v.x + v.y * v.y + v.z * v.z + v.w * v.w;
    }
#pragma unroll
    for (int off = 16; off; off >>= 1) {
        s  += __shfl_xor_sync(0xffffffffu, s,  off);
        s2 += __shfl_xor_sync(0xffffffffu, s2, off);
    }
    const float inv = 1.0f / (float)CC;
    float mu  = s * inv;
    float var = s2 * inv - mu * mu;
    float rstd = rsqrtf(var + 1e-5f);

    __half* arow = g_a + (size_t)gwarp * KP;
#pragma unroll
    for (int i = 0; i < 8; i++) {
        float4 v = vals[i];
        float4 w = wr[lane + i * 32];
        float4 b = br[lane + i * 32];
        float o0 = (v.x - mu) * rstd * w.x + b.x;
        float o1 = (v.y - mu) * rstd * w.y + b.y;
        float o2 = (v.z - mu) * rstd * w.z + b.z;
        float o3 = (v.w - mu) * rstd * w.w + b.w;
        int col = (lane + i * 32) * 4;
        *(__half2*)(arow + col)     = __halves2half2(__float2half_rn(o0), __float2half_rn(o1));
        *(__half2*)(arow + col + 2) = __halves2half2(__float2half_rn(o2), __float2half_rn(o3));
    }
}

// =================== weight conversion to fp16 ===================
__global__ void wconv(const float* __restrict__ Wk, const float* __restrict__ Wv,
                      const float* __restrict__ Wr, const float* __restrict__ Wo) {
    size_t idx  = (size_t)blockIdx.x * blockDim.x + threadIdx.x;
    size_t base = idx * 4;
    int w = (int)(base >> 20);
    size_t rem = base & 0xFFFFFu;
    const float* W = (w == 0) ? Wk : (w == 1) ? Wv : (w == 2) ? Wr : Wo;
    float4 v = *(const float4*)(W + rem);
    __half* dst = g_w + ((size_t)w << 20) + rem;
    *(__half2*)(dst)     = __halves2half2(__float2half_rn(v.x), __float2half_rn(v.y));
    *(__half2*)(dst + 2) = __halves2half2(__float2half_rn(v.z), __float2half_rn(v.w));
}

// ============== fp16 mma.sync NT GEMM: C[M,N] = A[M,K] * W[N,K]^T ==============
// 4 warps, warp tile 64x64, BK=64, XOR-swizzled 128B smem rows.
__global__ void __launch_bounds__(128)
gemm_mma(float* __restrict__ out, int isKVR) {
    extern __shared__ __align__(1024) char smem[];
    const uint32_t sbase = smem_u32(smem);

    const int tid  = threadIdx.x;
    const int lane = tid & 31;
    const int wid  = tid >> 5;
    const int wm   = wid & 1;     // 2 warp-rows (64 each)
    const int wn   = wid >> 1;    // 2 warp-cols (64 each)

    int col, w;
    if (isKVR) { w = blockIdx.x % 3; col = blockIdx.x / 3; }
    else       { w = 3;              col = blockIdx.x;     }
    const int brow = blockIdx.y * BM;
    const int bcol = col * BN;

    const __half* Abase = (isKVR ? g_a : g_att2) + (size_t)brow * KP;
    const __half* Wbase = g_w + ((size_t)w * CC + bcol) * KP;

    // ldmatrix per-lane swizzled address components.
    uint32_t abase[4], axor[4];
#pragma unroll
    for (int mt = 0; mt < 4; mt++) {
        int rowA = wm * 64 + mt * 16 + (lane & 15);
        int s = rowA & 7;
        abase[mt] = (uint32_t)(rowA * ROWB + (((lane >> 4) ^ (s & 1)) << 4));
        axor[mt]  = (uint32_t)((s & 6) << 4);
    }
    uint32_t bbase[4], bxor[4];
#pragma unroll
    for (int ntp = 0; ntp < 4; ntp++) {
        int rowB = wn * 64 + ntp * 16 + ((lane >> 4) << 3) + (lane & 7);
        int s = rowB & 7;
        bbase[ntp] = (uint32_t)(rowB * ROWB + ((((lane >> 3) & 1) ^ (s & 1)) << 4));
        bxor[ntp]  = (uint32_t)((s & 6) << 4);
    }

    float acc[4][8][4];
#pragma unroll
    for (int mt = 0; mt < 4; mt++)
#pragma unroll
        for (int nt = 0; nt < 8; nt++)
#pragma unroll
            for (int j = 0; j < 4; j++) acc[mt][nt][j] = 0.f;

    // ---- async load of one stage (128 threads: 8 A + 8 B cp16 each) ----
    auto load_stage = [&](int stg, int chunk) {
        uint32_t sA = sbase + stg * STG_SZ;
        uint32_t sB = sA + TILE_SZ;
        const __half* Ap = Abase + chunk * BK;
        const __half* Wp = Wbase + chunk * BK;
#pragma unroll
        for (int t = tid; t < 1024; t += 128) {
            int r = t >> 3, c = t & 7;
            uint32_t off = (uint32_t)(r * ROWB + ((c ^ (r & 7)) << 4));
            cp16(sA + off, Ap + (size_t)r * KP + c * 8);
            cp16(sB + off, Wp + (size_t)r * KP + c * 8);
        }
    };

    load_stage(0, 0); cp_commit();
    load_stage(1, 1); cp_commit();

    for (int i = 0; i < NCHUNKS; i++) {
        cp_wait1();
        __syncthreads();
        if (i + 2 < NCHUNKS) load_stage((i + 2) % NSTG, i + 2);
        cp_commit();

        uint32_t sA = sbase + (i % NSTG) * STG_SZ;
        uint32_t sB = sA + TILE_SZ;
#pragma unroll
        for (int kh = 0; kh < 4; kh++) {
            uint32_t kb = (uint32_t)(kh * 32);
            uint32_t af[4][4], bf[8][2];
#pragma unroll
            for (int mt = 0; mt < 4; mt++)
                ldm_x4(af[mt], sA + abase[mt] + (kb ^ axor[mt]));
#pragma unroll
            for (int ntp = 0; ntp < 4; ntp++) {
                uint32_t t4[4];
                ldm_x4(t4, sB + bbase[ntp] + (kb ^ bxor[ntp]));
                bf[ntp * 2 + 0][0] = t4[0]; bf[ntp * 2 + 0][1] = t4[1];
                bf[ntp * 2 + 1][0] = t4[2]; bf[ntp * 2 + 1][1] = t4[3];
            }
#pragma unroll
            for (int mt = 0; mt < 4; mt++)
#pragma unroll
                for (int nt = 0; nt < 8; nt++)
                    mma16816(acc[mt][nt], af[mt], bf[nt]);
        }
    }

    // ---- epilogue ----
    const int r0 = brow + wm * 64 + (lane >> 2);
    const int c0 = bcol + wn * 64 + (lane & 3) * 2;
    if (isKVR) {
        __half* Cm = (w == 0) ? g_k : (w == 1) ? g_v : g_r;
#pragma unroll
        for (int mt = 0; mt < 4; mt++) {
#pragma unroll
            for (int nt = 0; nt < 8; nt++) {
                __half* p0 = Cm + (size_t)(r0 + mt * 16) * CC + c0 + nt * 8;
                __half* p1 = p0 + 8 * CC;
                *(__half2*)p0 = __halves2half2(__float2half_rn(acc[mt][nt][0]),
                                               __float2half_rn(acc[mt][nt][1]));
                *(__half2*)p1 = __halves2half2(__float2half_rn(acc[mt][nt][2]),
                                               __float2half_rn(acc[mt][nt][3]));
            }
        }
    } else {
#pragma unroll
        for (int mt = 0; mt < 4; mt++) {
#pragma unroll
            for (int nt = 0; nt < 8; nt++) {
                float* p0 = out + (size_t)(r0 + mt * 16) * CC + c0 + nt * 8;
                float* p1 = p0 + 8 * CC;
                *(float2*)p0 = make_float2(acc[mt][nt][0], acc[mt][nt][1]);
                *(float2*)p1 = make_float2(acc[mt][nt][2], acc[mt][nt][3]);
            }
        }
    }
}

// ======================= WKV scan (chunked 2-pass, fp16 inputs) =======================
__global__ void scan_partial(const float* __restrict__ time_decay) {
    int c  = blockIdx.x * 256 + threadIdx.x;
    int ch = blockIdx.y;
    int b  = blockIdx.z;
    float td = -expf(time_decay[c]);
    size_t base = ((size_t)(b * TT + ch * CHUNK)) * CC + c;
    float s = 0.f;
#pragma unroll 4
    for (int i = 0; i < CHUNK; i++) {
        float t = (float)(ch * CHUNK + i);
        float w = expf(td * t);
        size_t id = base + (size_t)i * CC;
        s += __half2float(g_k[id]) * __half2float(g_v[id]) * w;
    }
    g_csum[((size_t)b * NCH + ch) * CC + c] = s;
}

// pass 2: inline exclusive chunk-prefix + replay; writes fp16 att
__global__ void scan_final(const float* __restrict__ time_decay,
                           const float* __restrict__ time_first) {
    int c  = blockIdx.x * 256 + threadIdx.x;
    int ch = blockIdx.y;
    int b  = blockIdx.z;
    float td = -expf(time_decay[c]);
    float tf = expf(time_first[c]);

    float state = 0.f;
    for (int j = 0; j < ch; j++)
        state += g_csum[((size_t)b * NCH + j) * CC + c];

    size_t rowbase = (size_t)(b * TT + ch * CHUNK);
#pragma unroll 4
    for (int i = 0; i < CHUNK; i++) {
        size_t id = (rowbase + i) * CC + c;
        float kk = __half2float(g_k[id]);
        float vv = __half2float(g_v[id]);
        float rr = __half2float(g_r[id]);
        float wgt = expf(td * (float)(ch * CHUNK + i));
        float sig = 1.0f / (1.0f + expf(-rr));
        float av  = sig * (state + kk * tf);
        state += kk * vv * wgt;
        g_att2[(rowbase + i) * KP + c] = __float2half_rn(av);
    }
}

// ================================ launch ================================
extern "C" void kernel_launch(void* const* d_in, const int* in_sizes, int n_in,
                              void* d_out, int out_size) {
    const float* x          = (const float*)d_in[0];
    const float* time_decay = (const float*)d_in[1];
    const float* time_first = (const float*)d_in[2];
    const float* Wk         = (const float*)d_in[3];
    const float* Wv         = (const float*)d_in[4];
    const float* Wr         = (const float*)d_in[5];
    const float* Wo         = (const float*)d_in[6];
    const float* ln_w       = (const float*)d_in[7];
    const float* ln_b       = (const float*)d_in[8];
    float* out = (float*)d_out;

    cudaFuncSetAttribute(gemm_mma, cudaFuncAttributeMaxDynamicSharedMemorySize, SMEM_DYN);

    // 1) LayerNorm -> g_a (fp16); weights -> g_w (fp16)
    ln_kernel<<<MROWS / 8, 256>>>(x, ln_w, ln_b);                 // launch #0
    wconv<<<4096, 256>>>(Wk, Wv, Wr, Wo);                         // launch #1
    nop_kernel<<<1, 32>>>();                                      // launch #2 (ncu align)

    // 2) k, v, r projections (launch #3 -> captured by ncu -s 5 -c 1)
    gemm_mma<<<dim3(24, MROWS / BM), 128, SMEM_DYN>>>(nullptr, 1);

    // 3) WKV scan (2-pass; final inlines the chunk-prefix)
    scan_partial<<<dim3(CC / 256, NCH, BB), 256>>>(time_decay);
    scan_final<<<dim3(CC / 256, NCH, BB), 256>>>(time_decay, time_first);

    // 4) output projection -> d_out
    gemm_mma<<<dim3(8, MROWS / BM), 128, SMEM_DYN>>>(out, 0);
}